// round 17
// baseline (speedup 1.0000x reference)
#include <cuda_runtime.h>
#include <cuda_fp16.h>
#include <cstdint>

// SMorph layer on HMMA (mma.sync m16n8k16 f16->f32), plain sm_100 target.
// Factorized via exp(p+k)=exp(p)exp(k):
//   den1=conv(E,A1)  num1=conv(PE,A1)+conv(E,B1)   (A=exp(k), B=k exp(k))
//   den2=conv(EM,A2) num2=conv(PEM,A2)+conv(EM,B2)
//   out = num1/den1 + num2/den2 + bias
// GEMM: D[m=pixel][n=0..63]; n: [0,16)=den1, [16,32)=num1, [32,48)=den2,
// [48,64)=num2. K/tap = 16 slots (12 maps + 4 zero). 9 taps = 9
// accumulating MMA groups, A base shifted by (kh*128+kw) pixels.
//
// Round 17: HMMA content measured at ~4.2us = the mma.sync roofline; the
// rest is fill/sync/epilogue phases where tensor idles. Phase compression:
// grid 252 (single wave, 2 tiles/CTA) with DOUBLE-BUFFERED A -- both tiles
// filled in ONE combined loop (LDG MLP ~4-6, 2 syncs/CTA instead of 4),
// then MMA0+epi0, MMA1+epi1 back-to-back as one long tensor stretch.

#define BATCH 8
#define CIN   3
#define HIN   128
#define WIN   128
#define FOUT  16
#define HOUT  126
#define WOUT  126

#define NT       256
#define ROWS_OUT 2
#define YTILES   63                 // HOUT / ROWS_OUT
#define NTILE    (BATCH * YTILES)   // 504 tiles
#define NPX      (4 * 128 + 8)      // 4 input rows + shift-overflow pad = 520
#define APITCH   48                 // bytes/pixel; 48-stride walks all 8 banks
#define A_BYTES  (NPX * APITCH)     // 24960
#define BPITCH   48
#define B_TAP    (64 * BPITCH)      // 3072
#define B_BYTES  (9 * B_TAP)        // 27648
#define SMEM_DYN (2 * A_BYTES + B_BYTES)   // 77568

__device__ __forceinline__ uint32_t smem_u32(const void* p) {
    uint32_t a;
    asm("{ .reg .u64 t; cvta.to.shared.u64 t, %1; cvt.u32.u64 %0, t; }"
        : "=r"(a) : "l"(p));
    return a;
}

__device__ __forceinline__ void ldm4(uint32_t* r, uint32_t addr) {
    asm volatile("ldmatrix.sync.aligned.m8n8.x4.shared.b16 {%0,%1,%2,%3}, [%4];"
                 : "=r"(r[0]), "=r"(r[1]), "=r"(r[2]), "=r"(r[3]) : "r"(addr));
}

__device__ __forceinline__ void mma16816(float* d, const uint32_t* a,
                                         const uint32_t* b) {
    asm volatile(
        "mma.sync.aligned.m16n8k16.row.col.f32.f16.f16.f32 "
        "{%0,%1,%2,%3}, {%4,%5,%6,%7}, {%8,%9}, {%0,%1,%2,%3};"
        : "+f"(d[0]), "+f"(d[1]), "+f"(d[2]), "+f"(d[3])
        : "r"(a[0]), "r"(a[1]), "r"(a[2]), "r"(a[3]), "r"(b[0]), "r"(b[1]));
}

__device__ __forceinline__ uint32_t pkh(__half a, __half b) {
    __half2 h = __halves2half2(a, b);
    return *reinterpret_cast<uint32_t*>(&h);
}

__global__ __launch_bounds__(NT, 2)
void smorph_hmma_kernel(const float* __restrict__ x,
                        const float* __restrict__ k1,
                        const float* __restrict__ k2,
                        const float* __restrict__ bias,
                        float* __restrict__ out)
{
    extern __shared__ char dsm[];
    char* smB = dsm + 2 * A_BYTES;

    const int tid  = threadIdx.x;
    const int wid  = tid >> 5;
    const int lane = tid & 31;
    const int cid  = blockIdx.x;

    // Tile coordinates for both tiles of this CTA
    const int T0 = cid * 2, T1 = T0 + 1;
    const int b0 = T0 / YTILES, r00 = (T0 - b0 * YTILES) * ROWS_OUT;
    const int b1 = T1 / YTILES, r01 = (T1 - b1 * YTILES) * ROWS_OUT;

    // ---- B zero -----------------------------------------------------------
    for (int i = tid; i < B_BYTES / 16; i += NT)
        reinterpret_cast<uint4*>(smB)[i] = make_uint4(0, 0, 0, 0);
    __syncthreads();

    // ---- B weight scatter. k-mem idx ((kh*3+kw)*3+c)*16+f ------------------
    for (int i = tid; i < 9 * CIN * FOUT; i += NT) {
        int f = i & 15, rest = i >> 4;       // rest = tap*3 + c
        int tap = rest / 3, c = rest - tap * 3;
        int gi = (tap * 3 + c) * FOUT + f;
        float w1 = k1[gi], w2 = k2[gi];
        float a1 = __expf(w1), a2 = __expf(w2);
        float bb1 = w1 * a1,  bb2 = w2 * a2;
        char* base = smB + tap * B_TAP;
#define BST(n, s, val) \
        *reinterpret_cast<__half*>(base + (n) * BPITCH + (s) * 2) = \
            __float2half_rn(val)
        BST(f,      c,     a1);     // den1:  E  * A1
        BST(16 + f, 3 + c, a1);     // num1:  PE * A1
        BST(16 + f, c,     bb1);    // num1:  E  * B1
        BST(32 + f, 6 + c, a2);     // den2:  EM * A2
        BST(48 + f, 9 + c, a2);     // num2: PEM * A2
        BST(48 + f, 6 + c, bb2);    // num2:  EM * B2
#undef BST
    }

    // ---- Combined A fill for BOTH tiles (one loop, high LDG MLP) ----------
    for (int i = tid; i < 2 * NPX; i += NT) {
        const int buf = (i >= NPX) ? 1 : 0;
        const int px  = i - buf * NPX;
        const int bb  = buf ? b1 : b0;
        const int r0  = buf ? r01 : r00;
        float m[12];
#pragma unroll
        for (int q = 0; q < 12; q++) m[q] = 0.0f;
        if (px < 512) {
            int row = px >> 7, xc = px & 127;
            int gy = r0 + row;               // r0<=124 -> gy<=127, in-bounds
#pragma unroll
            for (int c = 0; c < CIN; c++) {
                float v  = x[((bb * CIN + c) * HIN + gy) * WIN + xc];
                float e  = __expf(v);
                float em = __expf(-v);
                m[c]     = e;
                m[3 + c] = v * e;
                m[6 + c] = em;
                m[9 + c] = -v * em;
            }
        }
        uint32_t w[8];
#pragma unroll
        for (int j2 = 0; j2 < 6; j2++)
            w[j2] = pkh(__float2half_rn(m[2 * j2]),
                        __float2half_rn(m[2 * j2 + 1]));
        w[6] = 0u; w[7] = 0u;
        uint4* dst = reinterpret_cast<uint4*>(dsm + buf * A_BYTES + px * APITCH);
        dst[0] = make_uint4(w[0], w[1], w[2], w[3]);
        dst[1] = make_uint4(w[4], w[5], w[6], w[7]);
    }
    __syncthreads();   // covers B scatter + both A fills

    // ---- Lane-constant addresses ------------------------------------------
    const uint32_t aBase = smem_u32(dsm);
    const uint32_t bBase = smem_u32(smB);
    const int j = lane >> 3, r = lane & 7;
    const uint32_t aLane = aBase + (uint32_t)(((j & 1) * 8 + r) * APITCH +
                                              (j >> 1) * 16);
    const uint32_t bLane = bBase + (uint32_t)(((j >> 1) * 8 + r) * BPITCH +
                                              (j & 1) * 16);
    const uint32_t mOff0 = (uint32_t)((wid * 2) * 16 * APITCH);
    const uint32_t mOff1 = mOff0 + (uint32_t)(16 * APITCH);

    // ---- Two tiles: MMA + epilogue back-to-back (one long tensor phase) ---
#pragma unroll 1
    for (int t = 0; t < 2; t++) {
        const int bb = t ? b1 : b0;
        const int r0 = t ? r01 : r00;
        const uint32_t aT = aLane + (uint32_t)(t * A_BYTES);

        float d[2][8][4];
#pragma unroll
        for (int mc = 0; mc < 2; mc++)
#pragma unroll
            for (int nc = 0; nc < 8; nc++)
#pragma unroll
                for (int q = 0; q < 4; q++) d[mc][nc][q] = 0.0f;

        uint32_t af[2][2][4];                // [buf][mchunk][4]
        ldm4(af[0][0], aT + mOff0);          // tap 0: shift 0
        ldm4(af[0][1], aT + mOff1);

#pragma unroll
        for (int tap = 0; tap < 9; tap++) {
            const int cur = tap & 1, nxt = cur ^ 1;
            if (tap < 8) {
                const int kh = (tap + 1) / 3, kw = (tap + 1) - kh * 3;
                const uint32_t aN = aT + (uint32_t)((kh * 128 + kw) * APITCH);
                ldm4(af[nxt][0], aN + mOff0);
                ldm4(af[nxt][1], aN + mOff1);
            }
            const uint32_t bTap = bLane + (uint32_t)(tap * B_TAP);
            uint32_t bf[8][2];
#pragma unroll
            for (int q = 0; q < 4; q++) {
                uint32_t rg[4];
                ldm4(rg, bTap + (uint32_t)(q * 16 * BPITCH));
                bf[2 * q][0] = rg[0]; bf[2 * q][1] = rg[1];
                bf[2 * q + 1][0] = rg[2]; bf[2 * q + 1][1] = rg[3];
            }
#pragma unroll
            for (int nc = 0; nc < 8; nc++) {
                mma16816(d[0][nc], af[cur][0], bf[nc]);
                mma16816(d[1][nc], af[cur][1], bf[nc]);
            }
        }

        // ---- Epilogue: den/num for a given f in the SAME lane -------------
#pragma unroll
        for (int mc = 0; mc < 2; mc++) {
            const int mch = wid * 2 + mc;
#pragma unroll
            for (int h = 0; h < 2; h++) {
                const int mrow = mch * 16 + (lane >> 2) + h * 8;
                const int xc = mrow & 127;
                const int oh = r0 + (mrow >> 7);
                if (xc < WOUT) {
#pragma unroll
                    for (int g = 0; g < 2; g++) {
                        const int f = g * 8 + (lane & 3) * 2;
                        const float y0 =
                            __fdividef(d[mc][g + 2][2 * h], d[mc][g][2 * h]) +
                            __fdividef(d[mc][g + 6][2 * h],
                                       d[mc][g + 4][2 * h]) +
                            __ldg(bias + f);
                        const float y1 =
                            __fdividef(d[mc][g + 2][2 * h + 1],
                                       d[mc][g][2 * h + 1]) +
                            __fdividef(d[mc][g + 6][2 * h + 1],
                                       d[mc][g + 4][2 * h + 1]) +
                            __ldg(bias + f + 1);
                        out[((bb * FOUT + f) * HOUT + oh) * WOUT + xc] = y0;
                        out[((bb * FOUT + f + 1) * HOUT + oh) * WOUT + xc] = y1;
                    }
                }
            }
        }
    }
}

extern "C" void kernel_launch(void* const* d_in, const int* in_sizes, int n_in,
                              void* d_out, int out_size)
{
    const float* x    = (const float*)d_in[0];
    const float* k1   = (const float*)d_in[1];
    const float* k2   = (const float*)d_in[2];
    const float* bias = (const float*)d_in[3];
    float* out = (float*)d_out;

    cudaFuncSetAttribute(smorph_hmma_kernel,
                         cudaFuncAttributeMaxDynamicSharedMemorySize,
                         SMEM_DYN);

    smorph_hmma_kernel<<<NTILE / 2, NT, SMEM_DYN>>>(x, k1, k2, bias, out);
}